// round 16
// baseline (speedup 1.0000x reference)
#include <cuda_runtime.h>
#include <cuda_fp16.h>
#include <cstdint>

#define B_ 8
#define N_ 1024
#define D_ 512
#define H_ 8
#define DH_ 64
#define NW_ (N_/32)
#define L2E 1.4426950408889634f

// ---------------- scratch ----------------
__device__ unsigned short g_xn16[B_*N_*D_];     // LN1 out, fp16
__device__ unsigned short g_W16 [H_*DH_*D_];    // W^T [h][d][k], fp16
__device__ unsigned short g_hT16[B_*H_*DH_*N_]; // h^T [b][h][d][j], fp16
__device__ float    g_fs[B_*H_*N_];
__device__ float    g_fd[B_*H_*N_];
__device__ unsigned g_adjb[B_*N_*NW_];
__device__ float    g_y [B_*N_*D_];
__device__ float    g_A[B_*H_*N_];
__device__ float    g_C[B_*H_*N_];
__device__ float    g_u[B_*H_*N_];
__device__ float    g_v[B_*H_*N_];

// ---------------- helpers ----------------
__device__ __forceinline__ float fexp2f(float t) {
    t = fmaxf(t, -125.0f);
    float r = t + 12582912.0f;
    int   n = __float_as_int(r) - 0x4B400000;
    float f = t - (r - 12582912.0f);
    float p = 1.3333558146e-3f;
    p = fmaf(p, f, 9.6181291298e-3f);
    p = fmaf(p, f, 5.5504108664e-2f);
    p = fmaf(p, f, 2.4022650696e-1f);
    p = fmaf(p, f, 6.9314718056e-1f);
    p = fmaf(p, f, 1.0f);
    return __int_as_float(__float_as_int(p) + (n << 23));
}
__device__ __forceinline__ float elu1(float v) {
    return v > 0.0f ? v : (fexp2f(v * L2E) - 1.0f);
}
__device__ __forceinline__ unsigned smem_u32(const void* p) {
    unsigned a;
    asm("{ .reg .u64 t; cvta.to.shared.u64 t, %1; cvt.u32.u64 %0, t; }" : "=r"(a) : "l"(p));
    return a;
}
__device__ __forceinline__ void cpa16(unsigned s, const void* g) {
    asm volatile("cp.async.cg.shared.global [%0], [%1], 16;" :: "r"(s), "l"(g) : "memory");
}
#define CP_COMMIT() asm volatile("cp.async.commit_group;" ::: "memory")
#define CP_WAIT0()  asm volatile("cp.async.wait_group 0;" ::: "memory")
#define CP_WAIT1()  asm volatile("cp.async.wait_group 1;" ::: "memory")

__device__ __forceinline__ void mma16816h(float* c, unsigned a0, unsigned a1,
                                          unsigned a2, unsigned a3,
                                          unsigned b0, unsigned b1) {
    asm volatile(
        "mma.sync.aligned.m16n8k16.row.col.f32.f16.f16.f32 "
        "{%0,%1,%2,%3}, {%4,%5,%6,%7}, {%8,%9}, {%0,%1,%2,%3};\n"
        : "+f"(c[0]), "+f"(c[1]), "+f"(c[2]), "+f"(c[3])
        : "r"(a0), "r"(a1), "r"(a2), "r"(a3), "r"(b0), "r"(b1));
}
__device__ __forceinline__ void ldsm4(unsigned addr, unsigned &r0, unsigned &r1,
                                      unsigned &r2, unsigned &r3) {
    asm volatile("ldmatrix.sync.aligned.m8n8.x4.shared.b16 {%0,%1,%2,%3}, [%4];"
                 : "=r"(r0), "=r"(r1), "=r"(r2), "=r"(r3) : "r"(addr));
}

// ---- fp16 k32 step via ldmatrix (gemm1): A[128][32], B[64][32], stride 40 ----
__device__ __forceinline__ void mma_chunk_ss(float acc[8][4], unsigned A, unsigned B,
                                             int ibase, int lane) {
    int mat  = lane >> 3;
    int mrow = lane & 7;
#pragma unroll
    for (int kk = 0; kk < 2; kk++) {
        unsigned a0, a1, a2, a3;
        unsigned aaddr = A + (unsigned)(((ibase + (mat & 1) * 8 + mrow) * 40
                                         + kk * 16 + (mat >> 1) * 8) * 2);
        ldsm4(aaddr, a0, a1, a2, a3);
#pragma unroll
        for (int g = 0; g < 4; g++) {
            int ntp = g * 2;
            unsigned b0, b1, b2, b3;
            unsigned baddr = B + (unsigned)((((ntp + (mat >> 1)) * 8 + mrow) * 40
                                             + kk * 16 + (mat & 1) * 8) * 2);
            ldsm4(baddr, b0, b1, b2, b3);
            mma16816h(acc[ntp],     a0, a1, a2, a3, b0, b1);
            mma16816h(acc[ntp + 1], a0, a1, a2, a3, b2, b3);
        }
    }
}

// ---------------- LN1 (fp16 out) ----------------
__global__ void ln1_kernel(const float* __restrict__ x, const float* __restrict__ gw,
                           const float* __restrict__ bw) {
    int row = blockIdx.x, t = threadIdx.x;
    const float4 v = ((const float4*)(x + (size_t)row * D_))[t];
    float s = v.x + v.y + v.z + v.w;
    float q = v.x*v.x + v.y*v.y + v.z*v.z + v.w*v.w;
#pragma unroll
    for (int o = 16; o; o >>= 1) {
        s += __shfl_xor_sync(0xffffffffu, s, o);
        q += __shfl_xor_sync(0xffffffffu, q, o);
    }
    __shared__ float ss[4], qs[4];
    if ((t & 31) == 0) { ss[t >> 5] = s; qs[t >> 5] = q; }
    __syncthreads();
    s = ss[0] + ss[1] + ss[2] + ss[3];
    q = qs[0] + qs[1] + qs[2] + qs[3];
    float mean = s * (1.0f / D_);
    float var  = fmaxf(q * (1.0f / D_) - mean * mean, 0.0f);
    float inv  = 1.0f / (sqrtf(var) + 1e-6f);
    const float4 g4 = ((const float4*)gw)[t];
    const float4 b4 = ((const float4*)bw)[t];
    float o0 = fmaf(g4.x * (v.x - mean), inv, b4.x);
    float o1 = fmaf(g4.y * (v.y - mean), inv, b4.y);
    float o2 = fmaf(g4.z * (v.z - mean), inv, b4.z);
    float o3 = fmaf(g4.w * (v.w - mean), inv, b4.w);
    __half2 h01 = __floats2half2_rn(o0, o1);
    __half2 h23 = __floats2half2_rn(o2, o3);
    *(uint2*)&g_xn16[(size_t)row * D_ + t * 4] =
        make_uint2(*(unsigned*)&h01, *(unsigned*)&h23);
}

// ---------------- LN2 ----------------
__global__ void ln2_kernel(const float* __restrict__ gw, const float* __restrict__ bw,
                           float* __restrict__ out) {
    int row = blockIdx.x, t = threadIdx.x;
    const float4 v = ((const float4*)(g_y + (size_t)row * D_))[t];
    float s = v.x + v.y + v.z + v.w;
    float q = v.x*v.x + v.y*v.y + v.z*v.z + v.w*v.w;
#pragma unroll
    for (int o = 16; o; o >>= 1) {
        s += __shfl_xor_sync(0xffffffffu, s, o);
        q += __shfl_xor_sync(0xffffffffu, q, o);
    }
    __shared__ float ss[4], qs[4];
    if ((t & 31) == 0) { ss[t >> 5] = s; qs[t >> 5] = q; }
    __syncthreads();
    s = ss[0] + ss[1] + ss[2] + ss[3];
    q = qs[0] + qs[1] + qs[2] + qs[3];
    float mean = s * (1.0f / D_);
    float var  = fmaxf(q * (1.0f / D_) - mean * mean, 0.0f);
    float inv  = 1.0f / (sqrtf(var) + 1e-6f);
    const float4 g4 = ((const float4*)gw)[t];
    const float4 b4 = ((const float4*)bw)[t];
    float4 o;
    o.x = fmaf(g4.x * (v.x - mean), inv, b4.x);
    o.y = fmaf(g4.y * (v.y - mean), inv, b4.y);
    o.z = fmaf(g4.z * (v.z - mean), inv, b4.z);
    o.w = fmaf(g4.w * (v.w - mean), inv, b4.w);
    ((float4*)(out + (size_t)row * D_))[t] = o;
}

// ---------------- pack adj ----------------
__global__ void pack_adj_kernel(const int* __restrict__ adj) {
    int gw   = (blockIdx.x * blockDim.x + threadIdx.x) >> 5;
    int lane = threadIdx.x & 31;
    int v = adj[(size_t)gw * 32 + lane];
    unsigned m = __ballot_sync(0xffffffffu, v > 0);
    if (lane == 0) g_adjb[gw] = m;
}

// ---------------- W^T fp16 ----------------
__global__ void prep_w_kernel(const float* __restrict__ W) {
    int hd = blockIdx.x;
    int h = hd >> 6, d = hd & 63;
    for (int k = threadIdx.x; k < D_; k += 128) {
        float v = W[(size_t)h * D_ * DH_ + (size_t)k * DH_ + d];
        g_W16[(size_t)hd * D_ + k] = __half_as_ushort(__float2half_rn(v));
    }
}

// ---------------- GEMM1: fp16, k64 chunks, fused fs/fd + fused hT16 transpose ----
#define GM_DSM (2 * 30720)
__device__ __forceinline__ void g1_issue(unsigned sbase, int st, int c, int m0, int h, int t) {
    unsigned sb = sbase + (unsigned)st * 30720u;
    int k0 = c * 64;
#pragma unroll
    for (int i = t; i < 1536; i += 256) {
        const unsigned short* g;
        unsigned dst;
        if (i < 1024) {
            int tile = i >> 9;
            int idx = i & 511;
            int row = idx >> 2, seg = idx & 3;
            g = g_xn16 + (size_t)(m0 + row) * D_ + k0 + tile * 32 + seg * 8;
            dst = sb + tile * 10240u + row * 80u + seg * 16u;
        } else {
            int idx = i - 1024;
            int tile = idx >> 8;
            idx &= 255;
            int row = idx >> 2, seg = idx & 3;
            g = g_W16 + (size_t)(h * 64 + row) * D_ + k0 + tile * 32 + seg * 8;
            dst = sb + 20480u + tile * 5120u + row * 80u + seg * 16u;
        }
        cpa16(dst, g);
    }
}
__global__ __launch_bounds__(256, 3) void gemm1t_kernel(const float* __restrict__ a_src,
                                                        const float* __restrict__ a_dst) {
    extern __shared__ unsigned short dsm[];
    __shared__ float as_s[64], ad_s[64];
    unsigned sbase = smem_u32(dsm);
    int t = threadIdx.x, warp = t >> 5, lane = t & 31;
    int m0 = blockIdx.x * 128, h = blockIdx.y;
    int ibase = warp * 16;

    if (t < 64) as_s[t] = a_src[h * 64 + t];
    else if (t < 128) ad_s[t - 64] = a_dst[h * 64 + t - 64];

    float acc[8][4];
#pragma unroll
    for (int i = 0; i < 8; i++)
#pragma unroll
        for (int j = 0; j < 4; j++) acc[i][j] = 0.0f;

    g1_issue(sbase, 0, 0, m0, h, t); CP_COMMIT();

    for (int c = 0; c < 8; c++) {
        CP_WAIT0();
        __syncthreads();
        if (c + 1 < 8) { g1_issue(sbase, (c + 1) & 1, c + 1, m0, h, t); CP_COMMIT(); }
        unsigned stb = sbase + (unsigned)(c & 1) * 30720u;
        mma_chunk_ss(acc, stb,          stb + 20480u, ibase, lane);
        mma_chunk_ss(acc, stb + 10240u, stb + 25600u, ibase, lane);
    }

    int r = lane >> 2, q = lane & 3, c2 = q * 2;
    float fs1 = 0.f, fd1 = 0.f, fs2 = 0.f, fd2 = 0.f;
#pragma unroll
    for (int nt = 0; nt < 8; nt++) {
        float a0 = as_s[nt * 8 + c2], a1 = as_s[nt * 8 + c2 + 1];
        float d0 = ad_s[nt * 8 + c2], d1 = ad_s[nt * 8 + c2 + 1];
        fs1 = fmaf(acc[nt][0], a0, fmaf(acc[nt][1], a1, fs1));
        fd1 = fmaf(acc[nt][0], d0, fmaf(acc[nt][1], d1, fd1));
        fs2 = fmaf(acc[nt][2], a0, fmaf(acc[nt][3], a1, fs2));
        fd2 = fmaf(acc[nt][2], d0, fmaf(acc[nt][3], d1, fd2));
    }
#pragma unroll
    for (int o = 1; o <= 2; o <<= 1) {
        fs1 += __shfl_xor_sync(0xffffffffu, fs1, o);
        fd1 += __shfl_xor_sync(0xffffffffu, fd1, o);
        fs2 += __shfl_xor_sync(0xffffffffu, fs2, o);
        fd2 += __shfl_xor_sync(0xffffffffu, fd2, o);
    }
    if (q == 0) {
        int m1 = m0 + ibase + r, m2 = m1 + 8;
        int b1 = m1 >> 10, n1 = m1 & 1023;
        int b2 = m2 >> 10, n2 = m2 & 1023;
        g_fs[(b1 * H_ + h) * N_ + n1] = fs1 * L2E;
        g_fd[(b1 * H_ + h) * N_ + n1] = fd1 * L2E;
        g_fs[(b2 * H_ + h) * N_ + n2] = fs2 * L2E;
        g_fd[(b2 * H_ + h) * N_ + n2] = fd2 * L2E;
    }

    __syncthreads();
#pragma unroll
    for (int nt = 0; nt < 8; nt++) {
        int d0 = nt * 8 + c2;
        dsm[(d0    ) * 136 + ibase + r    ] = __half_as_ushort(__float2half_rn(acc[nt][0]));
        dsm[(d0 + 1) * 136 + ibase + r    ] = __half_as_ushort(__float2half_rn(acc[nt][1]));
        dsm[(d0    ) * 136 + ibase + r + 8] = __half_as_ushort(__float2half_rn(acc[nt][2]));
        dsm[(d0 + 1) * 136 + ibase + r + 8] = __half_as_ushort(__float2half_rn(acc[nt][3]));
    }
    __syncthreads();
    int b = m0 >> 10, n0 = m0 & 1023;
    size_t base = ((size_t)(b * H_ + h) * DH_) * N_ + n0;
#pragma unroll
    for (int k = 0; k < 4; k++) {
        int i = t + k * 256;
        int d = i >> 4, seg = i & 15;
        *(uint4*)&g_hT16[base + (size_t)d * N_ + seg * 8] =
            *(const uint4*)&dsm[d * 136 + seg * 8];
    }
}

// ---------------- merged gmax + uv ----------------
__global__ void gmaxuv_kernel() {
    __shared__ float sm[8];
    __shared__ float gmv;
    int bh = blockIdx.x, t = threadIdx.x;
    float fdv[4];
    float m = -1e30f;
#pragma unroll
    for (int k = 0; k < 4; k++) {
        fdv[k] = g_fd[bh * N_ + t + k * 256];
        m = fmaxf(m, fdv[k]);
    }
#pragma unroll
    for (int o = 16; o; o >>= 1) m = fmaxf(m, __shfl_xor_sync(0xffffffffu, m, o));
    if ((t & 31) == 0) sm[t >> 5] = m;
    __syncthreads();
    if (t == 0) {
        float mm = sm[0];
#pragma unroll
        for (int i = 1; i < 8; i++) mm = fmaxf(mm, sm[i]);
        gmv = mm;
    }
    __syncthreads();
    float gm = gmv;
#pragma unroll
    for (int k = 0; k < 4; k++) {
        int idx = bh * N_ + t + k * 256;
        float fs = g_fs[idx];
        float bound = fs + gm;
        float mx = fmaxf(bound, 0.2f * bound);
        g_A[idx] = fexp2f(bound - mx);
        g_C[idx] = fexp2f(0.2f * bound - mx);
        g_u[idx] = fexp2f(fdv[k] - gm);
        g_v[idx] = fexp2f(0.2f * (fdv[k] - gm));
    }
}

// ---------------- attention: i-tile 256, j-chunk 128 (4 subtiles), register P ----
// dsm: h stages 3*20480 B (each: 4 subs x 5120 B); uv floats @61440 B (8192 B).
// Total 69632 B -> 2 CTAs/SM, single wave (256 CTAs).
#define AT_DSM (3 * 20480 + 8192)
__device__ __forceinline__ void at_issue3(unsigned sbase, int st, int c, int bh, int t) {
    unsigned sb = sbase + (unsigned)st * 20480u;
    int j0 = c * 128;
#pragma unroll
    for (int i = t; i < 1024; i += 256) {
        int sub = i >> 8;
        int idx = i & 255;
        int row = idx >> 2, seg = idx & 3;
        const unsigned short* g = g_hT16 +
            (size_t)bh * DH_ * N_ + (size_t)row * N_ + j0 + sub * 32 + seg * 8;
        cpa16(sb + sub * 5120u + row * 80u + seg * 16u, g);
    }
}
__global__ __launch_bounds__(256, 2) void attn_kernel(const float* __restrict__ x) {
    extern __shared__ unsigned short dsm[];
    unsigned sbase = smem_u32(dsm);
    int t = threadIdx.x, warp = t >> 5, lane = t & 31;
    int b = blockIdx.z, h = blockIdx.y, i0 = blockIdx.x * 256;
    int bh = b * H_ + h;
    int ibase = warp * 32;
    int r = lane >> 2, c2 = (lane & 3) * 2;
    int mat = lane >> 3, mrow = lane & 7;
    int row0 = i0 + ibase + r;            // rows row0 + {0,8,16,24}

    const float* uvf = (const float*)(dsm + 30720);    // byte offset 61440

#pragma unroll
    for (int i = t; i < 512; i += 256) {
        const float* g = (i < 256) ? (g_u + bh * N_ + i * 4)
                                   : (g_v + bh * N_ + (i - 256) * 4);
        cpa16(sbase + 61440u + (unsigned)i * 16u, g);
    }
    CP_COMMIT();
    at_issue3(sbase, 0, 0, bh, t); CP_COMMIT();
    at_issue3(sbase, 1, 1, bh, t); CP_COMMIT();

    float fA[4], fC[4];
#pragma unroll
    for (int q = 0; q < 4; q++) {
        int rq = row0 + q * 8;
        fA[q] = g_A[bh * N_ + rq];
        fC[q] = g_C[bh * N_ + rq];
    }

    float acc[16][4];
#pragma unroll
    for (int i = 0; i < 16; i++)
#pragma unroll
        for (int j = 0; j < 4; j++) acc[i][j] = 0.0f;
    float den[4] = {0.f, 0.f, 0.f, 0.f};

    for (int c = 0; c < 8; c++) {
        if (c == 7) { CP_WAIT0(); } else { CP_WAIT1(); }
        __syncthreads();
        if (c + 2 < 8) { at_issue3(sbase, (c + 2) % 3, c + 2, bh, t); CP_COMMIT(); }
        unsigned hsb = sbase + (unsigned)(c % 3) * 20480u;
        unsigned w[4][4];
#pragma unroll
        for (int q = 0; q < 4; q++) {
            uint4 w4 = *(const uint4*)&g_adjb[(size_t)(b * N_ + row0 + q * 8) * NW_ + c * 4];
            w[q][0] = w4.x; w[q][1] = w4.y; w[q][2] = w4.z; w[q][3] = w4.w;
        }
#pragma unroll
        for (int sub = 0; sub < 4; sub++) {
            const float* us = uvf + c * 128 + sub * 32;
            const float* vs = uvf + 1024 + c * 128 + sub * 32;
            unsigned Bs = hsb + sub * 5120u;
#pragma unroll
            for (int kk = 0; kk < 2; kk++) {
                int jb = kk * 16 + c2;
                float2 u01 = *(const float2*)(us + jb);
                float2 u89 = *(const float2*)(us + jb + 8);
                float2 v01 = *(const float2*)(vs + jb);
                float2 v89 = *(const float2*)(vs + jb + 8);
                unsigned afr[2][4];
#pragma unroll
                for (int tile = 0; tile < 2; tile++) {
#pragma unroll
                    for (int rr = 0; rr < 2; rr++) {
                        int q = tile * 2 + rr;
                        unsigned wq = w[q][sub];
                        float p0 = ((wq >> (jb    )) & 1u) ? fmaxf(fA[q]*u01.x, fC[q]*v01.x) : 0.f;
                        float p1 = ((wq >> (jb + 1)) & 1u) ? fmaxf(fA[q]*u01.y, fC[q]*v01.y) : 0.f;
                        float p8 = ((wq >> (jb + 8)) & 1u) ? fmaxf(fA[q]*u89.x, fC[q]*v89.x) : 0.f;
                        float p9 = ((wq >> (jb + 9)) & 1u) ? fmaxf(fA[q]*u89.y, fC[q]*v89.y) : 0.f;
                        den[q] += (p0 + p1) + (p8 + p9);
                        __half2 lo = __floats2half2_rn(p0, p1);
                        __half2 hi = __floats2half2_rn(p8, p9);
                        afr[tile][rr]     = *(unsigned*)&lo;
                        afr[tile][2 + rr] = *(unsigned*)&hi;
                    }
                }
#pragma unroll
                for (int g = 0; g < 4; g++) {
                    int ntp = g * 2;
                    unsigned b0, b1, b2, b3;
                    unsigned baddr = Bs + (unsigned)((((ntp + (mat >> 1)) * 8 + mrow) * 40
                                                     + kk * 16 + (mat & 1) * 8) * 2);
                    ldsm4(baddr, b0, b1, b2, b3);
                    mma16816h(acc[ntp],         afr[0][0], afr[0][1], afr[0][2], afr[0][3], b0, b1);
                    mma16816h(acc[ntp + 1],     afr[0][0], afr[0][1], afr[0][2], afr[0][3], b2, b3);
                    mma16816h(acc[8 + ntp],     afr[1][0], afr[1][1], afr[1][2], afr[1][3], b0, b1);
                    mma16816h(acc[8 + ntp + 1], afr[1][0], afr[1][1], afr[1][2], afr[1][3], b2, b3);
                }
            }
        }
    }

#pragma unroll
    for (int q = 0; q < 4; q++) {
        den[q] += __shfl_xor_sync(0xffffffffu, den[q], 1);
        den[q] += __shfl_xor_sync(0xffffffffu, den[q], 2);
    }
    float inv0 = 1.0f / den[0], inv1 = 1.0f / den[1];
    float inv2 = 1.0f / den[2], inv3 = 1.0f / den[3];

#pragma unroll
    for (int nt = 0; nt < 8; nt++) {
        size_t i1 = (size_t)(b * N_ + row0     ) * D_ + h * DH_ + nt * 8 + c2;
        size_t i2 = (size_t)(b * N_ + row0 +  8) * D_ + h * DH_ + nt * 8 + c2;
        size_t i3 = (size_t)(b * N_ + row0 + 16) * D_ + h * DH_ + nt * 8 + c2;
        size_t i4 = (size_t)(b * N_ + row0 + 24) * D_ + h * DH_ + nt * 8 + c2;
        float2 x1 = *(const float2*)(x + i1);
        float2 x2 = *(const float2*)(x + i2);
        float2 x3 = *(const float2*)(x + i3);
        float2 x4 = *(const float2*)(x + i4);
        *(float2*)&g_y[i1] = make_float2(x1.x + elu1(acc[nt][0] * inv0),
                                         x1.y + elu1(acc[nt][1] * inv0));
        *(float2*)&g_y[i2] = make_float2(x2.x + elu1(acc[nt][2] * inv1),
                                         x2.y + elu1(acc[nt][3] * inv1));
        *(float2*)&g_y[i3] = make_float2(x3.x + elu1(acc[8 + nt][0] * inv2),
                                         x3.y + elu1(acc[8 + nt][1] * inv2));
        *(float2*)&g_y[i4] = make_float2(x4.x + elu1(acc[8 + nt][2] * inv3),
                                         x4.y + elu1(acc[8 + nt][3] * inv3));
    }
}

// ---------------- launch ----------------
extern "C" void kernel_launch(void* const* d_in, const int* in_sizes, int n_in,
                              void* d_out, int out_size) {
    const float* x     = (const float*)d_in[0];
    const int*   adj   = (const int*)  d_in[2];
    const float* W     = (const float*)d_in[3];
    const float* a_src = (const float*)d_in[4];
    const float* a_dst = (const float*)d_in[5];
    const float* ln1g  = (const float*)d_in[6];
    const float* ln1b  = (const float*)d_in[7];
    const float* ln2g  = (const float*)d_in[8];
    const float* ln2b  = (const float*)d_in[9];
    float* out = (float*)d_out;

    cudaFuncSetAttribute(gemm1t_kernel, cudaFuncAttributeMaxDynamicSharedMemorySize, GM_DSM);
    cudaFuncSetAttribute(attn_kernel,   cudaFuncAttributeMaxDynamicSharedMemorySize, AT_DSM);

    ln1_kernel   <<<B_*N_, 128>>>(x, ln1g, ln1b);
    pack_adj_kernel<<<(B_*N_*N_) / 256, 256>>>(adj);
    prep_w_kernel<<<H_*DH_, 128>>>(W);
    gemm1t_kernel<<<dim3(B_*N_/128, H_), 256, GM_DSM>>>(a_src, a_dst);
    gmaxuv_kernel<<<B_*H_, 256>>>();
    attn_kernel  <<<dim3(N_/256, H_, B_), 256, AT_DSM>>>(x);
    ln2_kernel   <<<B_*N_, 128>>>(ln2g, ln2b, out);
}

// round 17
// speedup vs baseline: 1.4212x; 1.4212x over previous
#include <cuda_runtime.h>
#include <cuda_fp16.h>
#include <cstdint>

#define B_ 8
#define N_ 1024
#define D_ 512
#define H_ 8
#define DH_ 64
#define NW_ (N_/32)
#define L2E 1.4426950408889634f

// ---------------- scratch ----------------
__device__ unsigned short g_xn16[B_*N_*D_];     // LN1 out, fp16
__device__ unsigned short g_W16 [H_*DH_*D_];    // W^T [h][d][k], fp16
__device__ unsigned short g_hT16[B_*H_*DH_*N_]; // h^T [b][h][d][j], fp16
__device__ float    g_fs[B_*H_*N_];
__device__ float    g_fd[B_*H_*N_];
__device__ unsigned g_adjb[B_*N_*NW_];
__device__ float    g_y [B_*N_*D_];
__device__ float    g_A[B_*H_*N_];
__device__ float    g_C[B_*H_*N_];
__device__ float    g_u[B_*H_*N_];
__device__ float    g_v[B_*H_*N_];

// ---------------- helpers ----------------
__device__ __forceinline__ float fexp2f(float t) {
    t = fmaxf(t, -125.0f);
    float r = t + 12582912.0f;
    int   n = __float_as_int(r) - 0x4B400000;
    float f = t - (r - 12582912.0f);
    float p = 1.3333558146e-3f;
    p = fmaf(p, f, 9.6181291298e-3f);
    p = fmaf(p, f, 5.5504108664e-2f);
    p = fmaf(p, f, 2.4022650696e-1f);
    p = fmaf(p, f, 6.9314718056e-1f);
    p = fmaf(p, f, 1.0f);
    return __int_as_float(__float_as_int(p) + (n << 23));
}
__device__ __forceinline__ float elu1(float v) {
    return v > 0.0f ? v : (fexp2f(v * L2E) - 1.0f);
}
__device__ __forceinline__ unsigned smem_u32(const void* p) {
    unsigned a;
    asm("{ .reg .u64 t; cvta.to.shared.u64 t, %1; cvt.u32.u64 %0, t; }" : "=r"(a) : "l"(p));
    return a;
}
__device__ __forceinline__ void cpa16(unsigned s, const void* g) {
    asm volatile("cp.async.cg.shared.global [%0], [%1], 16;" :: "r"(s), "l"(g) : "memory");
}
#define CP_COMMIT() asm volatile("cp.async.commit_group;" ::: "memory")
#define CP_WAIT0()  asm volatile("cp.async.wait_group 0;" ::: "memory")
#define CP_WAIT1()  asm volatile("cp.async.wait_group 1;" ::: "memory")

__device__ __forceinline__ void mma16816h(float* c, unsigned a0, unsigned a1,
                                          unsigned a2, unsigned a3,
                                          unsigned b0, unsigned b1) {
    asm volatile(
        "mma.sync.aligned.m16n8k16.row.col.f32.f16.f16.f32 "
        "{%0,%1,%2,%3}, {%4,%5,%6,%7}, {%8,%9}, {%0,%1,%2,%3};\n"
        : "+f"(c[0]), "+f"(c[1]), "+f"(c[2]), "+f"(c[3])
        : "r"(a0), "r"(a1), "r"(a2), "r"(a3), "r"(b0), "r"(b1));
}
__device__ __forceinline__ void ldsm4(unsigned addr, unsigned &r0, unsigned &r1,
                                      unsigned &r2, unsigned &r3) {
    asm volatile("ldmatrix.sync.aligned.m8n8.x4.shared.b16 {%0,%1,%2,%3}, [%4];"
                 : "=r"(r0), "=r"(r1), "=r"(r2), "=r"(r3) : "r"(addr));
}

// ---- fp16 k32 step via ldmatrix (gemm1): A[128][32], B[64][32], stride 40 ----
__device__ __forceinline__ void mma_chunk_ss(float acc[8][4], unsigned A, unsigned B,
                                             int ibase, int lane) {
    int mat  = lane >> 3;
    int mrow = lane & 7;
#pragma unroll
    for (int kk = 0; kk < 2; kk++) {
        unsigned a0, a1, a2, a3;
        unsigned aaddr = A + (unsigned)(((ibase + (mat & 1) * 8 + mrow) * 40
                                         + kk * 16 + (mat >> 1) * 8) * 2);
        ldsm4(aaddr, a0, a1, a2, a3);
#pragma unroll
        for (int g = 0; g < 4; g++) {
            int ntp = g * 2;
            unsigned b0, b1, b2, b3;
            unsigned baddr = B + (unsigned)((((ntp + (mat >> 1)) * 8 + mrow) * 40
                                             + kk * 16 + (mat & 1) * 8) * 2);
            ldsm4(baddr, b0, b1, b2, b3);
            mma16816h(acc[ntp],     a0, a1, a2, a3, b0, b1);
            mma16816h(acc[ntp + 1], a0, a1, a2, a3, b2, b3);
        }
    }
}

// ---------------- LN1 (fp16 out) ----------------
__global__ void ln1_kernel(const float* __restrict__ x, const float* __restrict__ gw,
                           const float* __restrict__ bw) {
    int row = blockIdx.x, t = threadIdx.x;
    const float4 v = ((const float4*)(x + (size_t)row * D_))[t];
    float s = v.x + v.y + v.z + v.w;
    float q = v.x*v.x + v.y*v.y + v.z*v.z + v.w*v.w;
#pragma unroll
    for (int o = 16; o; o >>= 1) {
        s += __shfl_xor_sync(0xffffffffu, s, o);
        q += __shfl_xor_sync(0xffffffffu, q, o);
    }
    __shared__ float ss[4], qs[4];
    if ((t & 31) == 0) { ss[t >> 5] = s; qs[t >> 5] = q; }
    __syncthreads();
    s = ss[0] + ss[1] + ss[2] + ss[3];
    q = qs[0] + qs[1] + qs[2] + qs[3];
    float mean = s * (1.0f / D_);
    float var  = fmaxf(q * (1.0f / D_) - mean * mean, 0.0f);
    float inv  = 1.0f / (sqrtf(var) + 1e-6f);
    const float4 g4 = ((const float4*)gw)[t];
    const float4 b4 = ((const float4*)bw)[t];
    float o0 = fmaf(g4.x * (v.x - mean), inv, b4.x);
    float o1 = fmaf(g4.y * (v.y - mean), inv, b4.y);
    float o2 = fmaf(g4.z * (v.z - mean), inv, b4.z);
    float o3 = fmaf(g4.w * (v.w - mean), inv, b4.w);
    __half2 h01 = __floats2half2_rn(o0, o1);
    __half2 h23 = __floats2half2_rn(o2, o3);
    *(uint2*)&g_xn16[(size_t)row * D_ + t * 4] =
        make_uint2(*(unsigned*)&h01, *(unsigned*)&h23);
}

// ---------------- LN2 ----------------
__global__ void ln2_kernel(const float* __restrict__ gw, const float* __restrict__ bw,
                           float* __restrict__ out) {
    int row = blockIdx.x, t = threadIdx.x;
    const float4 v = ((const float4*)(g_y + (size_t)row * D_))[t];
    float s = v.x + v.y + v.z + v.w;
    float q = v.x*v.x + v.y*v.y + v.z*v.z + v.w*v.w;
#pragma unroll
    for (int o = 16; o; o >>= 1) {
        s += __shfl_xor_sync(0xffffffffu, s, o);
        q += __shfl_xor_sync(0xffffffffu, q, o);
    }
    __shared__ float ss[4], qs[4];
    if ((t & 31) == 0) { ss[t >> 5] = s; qs[t >> 5] = q; }
    __syncthreads();
    s = ss[0] + ss[1] + ss[2] + ss[3];
    q = qs[0] + qs[1] + qs[2] + qs[3];
    float mean = s * (1.0f / D_);
    float var  = fmaxf(q * (1.0f / D_) - mean * mean, 0.0f);
    float inv  = 1.0f / (sqrtf(var) + 1e-6f);
    const float4 g4 = ((const float4*)gw)[t];
    const float4 b4 = ((const float4*)bw)[t];
    float4 o;
    o.x = fmaf(g4.x * (v.x - mean), inv, b4.x);
    o.y = fmaf(g4.y * (v.y - mean), inv, b4.y);
    o.z = fmaf(g4.z * (v.z - mean), inv, b4.z);
    o.w = fmaf(g4.w * (v.w - mean), inv, b4.w);
    ((float4*)(out + (size_t)row * D_))[t] = o;
}

// ---------------- pack adj ----------------
__global__ void pack_adj_kernel(const int* __restrict__ adj) {
    int gw   = (blockIdx.x * blockDim.x + threadIdx.x) >> 5;
    int lane = threadIdx.x & 31;
    int v = adj[(size_t)gw * 32 + lane];
    unsigned m = __ballot_sync(0xffffffffu, v > 0);
    if (lane == 0) g_adjb[gw] = m;
}

// ---------------- W^T fp16 ----------------
__global__ void prep_w_kernel(const float* __restrict__ W) {
    int hd = blockIdx.x;
    int h = hd >> 6, d = hd & 63;
    for (int k = threadIdx.x; k < D_; k += 128) {
        float v = W[(size_t)h * D_ * DH_ + (size_t)k * DH_ + d];
        g_W16[(size_t)hd * D_ + k] = __half_as_ushort(__float2half_rn(v));
    }
}

// ---------------- GEMM1: fp16, k64 chunks, fused fs/fd + fused hT16 transpose ----
#define GM_DSM (2 * 30720)
__device__ __forceinline__ void g1_issue(unsigned sbase, int st, int c, int m0, int h, int t) {
    unsigned sb = sbase + (unsigned)st * 30720u;
    int k0 = c * 64;
#pragma unroll
    for (int i = t; i < 1536; i += 256) {
        const unsigned short* g;
        unsigned dst;
        if (i < 1024) {
            int tile = i >> 9;
            int idx = i & 511;
            int row = idx >> 2, seg = idx & 3;
            g = g_xn16 + (size_t)(m0 + row) * D_ + k0 + tile * 32 + seg * 8;
            dst = sb + tile * 10240u + row * 80u + seg * 16u;
        } else {
            int idx = i - 1024;
            int tile = idx >> 8;
            idx &= 255;
            int row = idx >> 2, seg = idx & 3;
            g = g_W16 + (size_t)(h * 64 + row) * D_ + k0 + tile * 32 + seg * 8;
            dst = sb + 20480u + tile * 5120u + row * 80u + seg * 16u;
        }
        cpa16(dst, g);
    }
}
__global__ __launch_bounds__(256, 3) void gemm1t_kernel(const float* __restrict__ a_src,
                                                        const float* __restrict__ a_dst) {
    extern __shared__ unsigned short dsm[];
    __shared__ float as_s[64], ad_s[64];
    unsigned sbase = smem_u32(dsm);
    int t = threadIdx.x, warp = t >> 5, lane = t & 31;
    int m0 = blockIdx.x * 128, h = blockIdx.y;
    int ibase = warp * 16;

    if (t < 64) as_s[t] = a_src[h * 64 + t];
    else if (t < 128) ad_s[t - 64] = a_dst[h * 64 + t - 64];

    float acc[8][4];
#pragma unroll
    for (int i = 0; i < 8; i++)
#pragma unroll
        for (int j = 0; j < 4; j++) acc[i][j] = 0.0f;

    g1_issue(sbase, 0, 0, m0, h, t); CP_COMMIT();

    for (int c = 0; c < 8; c++) {
        CP_WAIT0();
        __syncthreads();
        if (c + 1 < 8) { g1_issue(sbase, (c + 1) & 1, c + 1, m0, h, t); CP_COMMIT(); }
        unsigned stb = sbase + (unsigned)(c & 1) * 30720u;
        mma_chunk_ss(acc, stb,          stb + 20480u, ibase, lane);
        mma_chunk_ss(acc, stb + 10240u, stb + 25600u, ibase, lane);
    }

    int r = lane >> 2, q = lane & 3, c2 = q * 2;
    float fs1 = 0.f, fd1 = 0.f, fs2 = 0.f, fd2 = 0.f;
#pragma unroll
    for (int nt = 0; nt < 8; nt++) {
        float a0 = as_s[nt * 8 + c2], a1 = as_s[nt * 8 + c2 + 1];
        float d0 = ad_s[nt * 8 + c2], d1 = ad_s[nt * 8 + c2 + 1];
        fs1 = fmaf(acc[nt][0], a0, fmaf(acc[nt][1], a1, fs1));
        fd1 = fmaf(acc[nt][0], d0, fmaf(acc[nt][1], d1, fd1));
        fs2 = fmaf(acc[nt][2], a0, fmaf(acc[nt][3], a1, fs2));
        fd2 = fmaf(acc[nt][2], d0, fmaf(acc[nt][3], d1, fd2));
    }
#pragma unroll
    for (int o = 1; o <= 2; o <<= 1) {
        fs1 += __shfl_xor_sync(0xffffffffu, fs1, o);
        fd1 += __shfl_xor_sync(0xffffffffu, fd1, o);
        fs2 += __shfl_xor_sync(0xffffffffu, fs2, o);
        fd2 += __shfl_xor_sync(0xffffffffu, fd2, o);
    }
    if (q == 0) {
        int m1 = m0 + ibase + r, m2 = m1 + 8;
        int b1 = m1 >> 10, n1 = m1 & 1023;
        int b2 = m2 >> 10, n2 = m2 & 1023;
        g_fs[(b1 * H_ + h) * N_ + n1] = fs1 * L2E;
        g_fd[(b1 * H_ + h) * N_ + n1] = fd1 * L2E;
        g_fs[(b2 * H_ + h) * N_ + n2] = fs2 * L2E;
        g_fd[(b2 * H_ + h) * N_ + n2] = fd2 * L2E;
    }

    __syncthreads();
#pragma unroll
    for (int nt = 0; nt < 8; nt++) {
        int d0 = nt * 8 + c2;
        dsm[(d0    ) * 136 + ibase + r    ] = __half_as_ushort(__float2half_rn(acc[nt][0]));
        dsm[(d0 + 1) * 136 + ibase + r    ] = __half_as_ushort(__float2half_rn(acc[nt][1]));
        dsm[(d0    ) * 136 + ibase + r + 8] = __half_as_ushort(__float2half_rn(acc[nt][2]));
        dsm[(d0 + 1) * 136 + ibase + r + 8] = __half_as_ushort(__float2half_rn(acc[nt][3]));
    }
    __syncthreads();
    int b = m0 >> 10, n0 = m0 & 1023;
    size_t base = ((size_t)(b * H_ + h) * DH_) * N_ + n0;
#pragma unroll
    for (int k = 0; k < 4; k++) {
        int i = t + k * 256;
        int d = i >> 4, seg = i & 15;
        *(uint4*)&g_hT16[base + (size_t)d * N_ + seg * 8] =
            *(const uint4*)&dsm[d * 136 + seg * 8];
    }
}

// ---------------- merged gmax + uv ----------------
__global__ void gmaxuv_kernel() {
    __shared__ float sm[8];
    __shared__ float gmv;
    int bh = blockIdx.x, t = threadIdx.x;
    float fdv[4];
    float m = -1e30f;
#pragma unroll
    for (int k = 0; k < 4; k++) {
        fdv[k] = g_fd[bh * N_ + t + k * 256];
        m = fmaxf(m, fdv[k]);
    }
#pragma unroll
    for (int o = 16; o; o >>= 1) m = fmaxf(m, __shfl_xor_sync(0xffffffffu, m, o));
    if ((t & 31) == 0) sm[t >> 5] = m;
    __syncthreads();
    if (t == 0) {
        float mm = sm[0];
#pragma unroll
        for (int i = 1; i < 8; i++) mm = fmaxf(mm, sm[i]);
        gmv = mm;
    }
    __syncthreads();
    float gm = gmv;
#pragma unroll
    for (int k = 0; k < 4; k++) {
        int idx = bh * N_ + t + k * 256;
        float fs = g_fs[idx];
        float bound = fs + gm;
        float mx = fmaxf(bound, 0.2f * bound);
        g_A[idx] = fexp2f(bound - mx);
        g_C[idx] = fexp2f(0.2f * bound - mx);
        g_u[idx] = fexp2f(fdv[k] - gm);
        g_v[idx] = fexp2f(0.2f * (fdv[k] - gm));
    }
}

// ---------------- attention: i-tile 256, j-chunk 128, register P, lean adj ----
// dsm: h stages 3*20480 B (each: 4 subs x 5120 B); uv floats @61440 B (8192 B).
// Total 69632 B -> 2 CTAs/SM, single wave (256 CTAs).
#define AT_DSM (3 * 20480 + 8192)
__device__ __forceinline__ void at_issue3(unsigned sbase, int st, int c, int bh, int t) {
    unsigned sb = sbase + (unsigned)st * 20480u;
    int j0 = c * 128;
#pragma unroll
    for (int i = t; i < 1024; i += 256) {
        int sub = i >> 8;
        int idx = i & 255;
        int row = idx >> 2, seg = idx & 3;
        const unsigned short* g = g_hT16 +
            (size_t)bh * DH_ * N_ + (size_t)row * N_ + j0 + sub * 32 + seg * 8;
        cpa16(sb + sub * 5120u + row * 80u + seg * 16u, g);
    }
}
__global__ __launch_bounds__(256, 2) void attn_kernel(const float* __restrict__ x) {
    extern __shared__ unsigned short dsm[];
    unsigned sbase = smem_u32(dsm);
    int t = threadIdx.x, warp = t >> 5, lane = t & 31;
    int b = blockIdx.z, h = blockIdx.y, i0 = blockIdx.x * 256;
    int bh = b * H_ + h;
    int ibase = warp * 32;
    int r = lane >> 2, c2 = (lane & 3) * 2;
    int mat = lane >> 3, mrow = lane & 7;
    int row0 = i0 + ibase + r;            // rows row0 + {0,8,16,24}

    const float* uvf = (const float*)(dsm + 30720);    // byte offset 61440

#pragma unroll
    for (int i = t; i < 512; i += 256) {
        const float* g = (i < 256) ? (g_u + bh * N_ + i * 4)
                                   : (g_v + bh * N_ + (i - 256) * 4);
        cpa16(sbase + 61440u + (unsigned)i * 16u, g);
    }
    CP_COMMIT();
    at_issue3(sbase, 0, 0, bh, t); CP_COMMIT();
    at_issue3(sbase, 1, 1, bh, t); CP_COMMIT();

    float fA[4], fC[4];
#pragma unroll
    for (int q = 0; q < 4; q++) {
        int rq = row0 + q * 8;
        fA[q] = g_A[bh * N_ + rq];
        fC[q] = g_C[bh * N_ + rq];
    }

    float acc[16][4];
#pragma unroll
    for (int i = 0; i < 16; i++)
#pragma unroll
        for (int j = 0; j < 4; j++) acc[i][j] = 0.0f;
    float den[4] = {0.f, 0.f, 0.f, 0.f};

    for (int c = 0; c < 8; c++) {
        if (c == 7) { CP_WAIT0(); } else { CP_WAIT1(); }
        __syncthreads();
        if (c + 2 < 8) { at_issue3(sbase, (c + 2) % 3, c + 2, bh, t); CP_COMMIT(); }
        unsigned hsb = sbase + (unsigned)(c % 3) * 20480u;
#pragma unroll
        for (int sub = 0; sub < 4; sub++) {
            // adjacency words loaded at point of use (quad-uniform, L1-resident)
            unsigned wq_[4];
#pragma unroll
            for (int q = 0; q < 4; q++)
                wq_[q] = g_adjb[(size_t)(b * N_ + row0 + q * 8) * NW_ + c * 4 + sub];
            const float* us = uvf + c * 128 + sub * 32;
            const float* vs = uvf + 1024 + c * 128 + sub * 32;
            unsigned Bs = hsb + sub * 5120u;
#pragma unroll
            for (int kk = 0; kk < 2; kk++) {
                int jb = kk * 16 + c2;
                float2 u01 = *(const float2*)(us + jb);
                float2 u89 = *(const float2*)(us + jb + 8);
                float2 v01 = *(const float2*)(vs + jb);
                float2 v89 = *(const float2*)(vs + jb + 8);
                unsigned afr[2][4];
#pragma unroll
                for (int tile = 0; tile < 2; tile++) {
#pragma unroll
                    for (int rr = 0; rr < 2; rr++) {
                        int q = tile * 2 + rr;
                        unsigned wq = wq_[q];
                        float p0 = ((wq >> (jb    )) & 1u) ? fmaxf(fA[q]*u01.x, fC[q]*v01.x) : 0.f;
                        float p1 = ((wq >> (jb + 1)) & 1u) ? fmaxf(fA[q]*u01.y, fC[q]*v01.y) : 0.f;
                        float p8 = ((wq >> (jb + 8)) & 1u) ? fmaxf(fA[q]*u89.x, fC[q]*v89.x) : 0.f;
                        float p9 = ((wq >> (jb + 9)) & 1u) ? fmaxf(fA[q]*u89.y, fC[q]*v89.y) : 0.f;
                        den[q] += (p0 + p1) + (p8 + p9);
                        __half2 lo = __floats2half2_rn(p0, p1);
                        __half2 hi = __floats2half2_rn(p8, p9);
                        afr[tile][rr]     = *(unsigned*)&lo;
                        afr[tile][2 + rr] = *(unsigned*)&hi;
                    }
                }
#pragma unroll
                for (int g = 0; g < 4; g++) {
                    int ntp = g * 2;
                    unsigned b0, b1, b2, b3;
                    unsigned baddr = Bs + (unsigned)((((ntp + (mat >> 1)) * 8 + mrow) * 40
                                                     + kk * 16 + (mat & 1) * 8) * 2);
                    ldsm4(baddr, b0, b1, b2, b3);
                    mma16816h(acc[ntp],         afr[0][0], afr[0][1], afr[0][2], afr[0][3], b0, b1);
                    mma16816h(acc[ntp + 1],     afr[0][0], afr[0][1], afr[0][2], afr[0][3], b2, b3);
                    mma16816h(acc[8 + ntp],     afr[1][0], afr[1][1], afr[1][2], afr[1][3], b0, b1);
                    mma16816h(acc[8 + ntp + 1], afr[1][0], afr[1][1], afr[1][2], afr[1][3], b2, b3);
                }
            }
        }
    }

#pragma unroll
    for (int q = 0; q < 4; q++) {
        den[q] += __shfl_xor_sync(0xffffffffu, den[q], 1);
        den[q] += __shfl_xor_sync(0xffffffffu, den[q], 2);
    }
    float inv0 = 1.0f / den[0], inv1 = 1.0f / den[1];
    float inv2 = 1.0f / den[2], inv3 = 1.0f / den[3];

#pragma unroll
    for (int nt = 0; nt < 8; nt++) {
        size_t i1 = (size_t)(b * N_ + row0     ) * D_ + h * DH_ + nt * 8 + c2;
        size_t i2 = (size_t)(b * N_ + row0 +  8) * D_ + h * DH_ + nt * 8 + c2;
        size_t i3 = (size_t)(b * N_ + row0 + 16) * D_ + h * DH_ + nt * 8 + c2;
        size_t i4 = (size_t)(b * N_ + row0 + 24) * D_ + h * DH_ + nt * 8 + c2;
        float2 x1 = *(const float2*)(x + i1);
        float2 x2 = *(const float2*)(x + i2);
        float2 x3 = *(const float2*)(x + i3);
        float2 x4 = *(const float2*)(x + i4);
        *(float2*)&g_y[i1] = make_float2(x1.x + elu1(acc[nt][0] * inv0),
                                         x1.y + elu1(acc[nt][1] * inv0));
        *(float2*)&g_y[i2] = make_float2(x2.x + elu1(acc[nt][2] * inv1),
                                         x2.y + elu1(acc[nt][3] * inv1));
        *(float2*)&g_y[i3] = make_float2(x3.x + elu1(acc[8 + nt][0] * inv2),
                                         x3.y + elu1(acc[8 + nt][1] * inv2));
        *(float2*)&g_y[i4] = make_float2(x4.x + elu1(acc[8 + nt][2] * inv3),
                                         x4.y + elu1(acc[8 + nt][3] * inv3));
    }
}

// ---------------- launch ----------------
extern "C" void kernel_launch(void* const* d_in, const int* in_sizes, int n_in,
                              void* d_out, int out_size) {
    const float* x     = (const float*)d_in[0];
    const int*   adj   = (const int*)  d_in[2];
    const float* W     = (const float*)d_in[3];
    const float* a_src = (const float*)d_in[4];
    const float* a_dst = (const float*)d_in[5];
    const float* ln1g  = (const float*)d_in[6];
    const float* ln1b  = (const float*)d_in[7];
    const float* ln2g  = (const float*)d_in[8];
    const float* ln2b  = (const float*)d_in[9];
    float* out = (float*)d_out;

    cudaFuncSetAttribute(gemm1t_kernel, cudaFuncAttributeMaxDynamicSharedMemorySize, GM_DSM);
    cudaFuncSetAttribute(attn_kernel,   cudaFuncAttributeMaxDynamicSharedMemorySize, AT_DSM);

    ln1_kernel   <<<B_*N_, 128>>>(x, ln1g, ln1b);
    pack_adj_kernel<<<(B_*N_*N_) / 256, 256>>>(adj);
    prep_w_kernel<<<H_*DH_, 128>>>(W);
    gemm1t_kernel<<<dim3(B_*N_/128, H_), 256, GM_DSM>>>(a_src, a_dst);
    gmaxuv_kernel<<<B_*H_, 256>>>();
    attn_kernel  <<<dim3(N_/256, H_, B_), 256, AT_DSM>>>(x);
    ln2_kernel   <<<B_*N_, 128>>>(ln2g, ln2b, out);
}